// round 1
// baseline (speedup 1.0000x reference)
#include <cuda_runtime.h>
#include <math.h>

// Problem constants (fixed by the reference setup_inputs)
constexpr int NN  = 100000;   // nodes
constexpr int NE  = 3200000;  // edges
constexpr int FIN = 21;       // input features
constexpr int FP  = 24;       // padded input features (96B rows, 16B-aligned)
constexpr int H1  = 32;
constexpr int H2  = 8;

// Scratch (device globals; no allocation allowed)
__device__ float g_deg [NN];
__device__ float g_dinv[NN];
__device__ __align__(16) float g_xp  [NN * FP];  // padded x
__device__ __align__(16) float g_agg1[NN * FP];  // layer-1 aggregation (pre-transform)
__device__ __align__(16) float g_t   [NN * H2];  // h1 @ W2 (pre-aggregation)
__device__ __align__(16) float g_agg2[NN * H2];
__device__ __align__(16) float g_h2  [NN * H2];  // final node embeddings

// ---------------------------------------------------------------------------
__global__ void k_deg_init() {
    int i = blockIdx.x * blockDim.x + threadIdx.x;
    if (i < NN) g_deg[i] = 1.0f;  // self-loop
}

__global__ void k_deg(const int* __restrict__ dst) {
    int e = blockIdx.x * blockDim.x + threadIdx.x;
    if (e < NE) atomicAdd(&g_deg[dst[e]], 1.0f);
}

__global__ void k_dinv() {
    int i = blockIdx.x * blockDim.x + threadIdx.x;
    if (i < NN) g_dinv[i] = rsqrtf(g_deg[i]);
}

// Pad x into 24-float rows; init agg1 with the self-loop contribution x[i]*dinv[i]^2
__global__ void k_prep(const float* __restrict__ x) {
    int tid = blockIdx.x * blockDim.x + threadIdx.x;
    if (tid >= NN * FP) return;
    int i = tid / FP;
    int f = tid - i * FP;
    float v = (f < FIN) ? x[i * FIN + f] : 0.0f;
    g_xp[tid] = v;
    float di = g_dinv[i];
    g_agg1[tid] = v * di * di;
}

// Layer-1 edge aggregation: agg1[dst] += x[src] * dinv[src]*dinv[dst]
__global__ void k_agg1(const int* __restrict__ src, const int* __restrict__ dst) {
    int e = blockIdx.x * blockDim.x + threadIdx.x;
    if (e >= NE) return;
    int s = src[e];
    int d = dst[e];
    float w = g_dinv[s] * g_dinv[d];
    const float4* __restrict__ xr = reinterpret_cast<const float4*>(g_xp + (size_t)s * FP);
    float4* out = reinterpret_cast<float4*>(g_agg1 + (size_t)d * FP);
#pragma unroll
    for (int j = 0; j < FP / 4; j++) {
        float4 v = xr[j];
        atomicAdd(out + j, make_float4(v.x * w, v.y * w, v.z * w, v.w * w));
    }
}

// Per node: h1 = relu(agg1 @ W1 + b1); t = h1 @ W2; agg2 init = t * dinv^2
__global__ void k_layer(const float* __restrict__ W1, const float* __restrict__ b1,
                        const float* __restrict__ W2) {
    __shared__ float sW1[FIN * H1];
    __shared__ float sW2[H1 * H2];
    __shared__ float sb1[H1];
    for (int j = threadIdx.x; j < FIN * H1; j += blockDim.x) sW1[j] = W1[j];
    for (int j = threadIdx.x; j < H1 * H2; j += blockDim.x) sW2[j] = W2[j];
    for (int j = threadIdx.x; j < H1; j += blockDim.x) sb1[j] = b1[j];
    __syncthreads();

    int i = blockIdx.x * blockDim.x + threadIdx.x;
    if (i >= NN) return;

    float a[FIN];
    const float* __restrict__ arow = g_agg1 + (size_t)i * FP;
#pragma unroll
    for (int f = 0; f < FIN; f++) a[f] = arow[f];

    float t[H2];
#pragma unroll
    for (int j = 0; j < H2; j++) t[j] = 0.0f;

#pragma unroll
    for (int k = 0; k < H1; k++) {
        float acc = sb1[k];
#pragma unroll
        for (int f = 0; f < FIN; f++) acc = fmaf(a[f], sW1[f * H1 + k], acc);
        acc = fmaxf(acc, 0.0f);  // ReLU
#pragma unroll
        for (int j = 0; j < H2; j++) t[j] = fmaf(acc, sW2[k * H2 + j], t[j]);
    }

    float di = g_dinv[i];
    float n = di * di;
    float* trow = g_t + (size_t)i * H2;
    float* grow = g_agg2 + (size_t)i * H2;
#pragma unroll
    for (int j = 0; j < H2; j++) {
        trow[j] = t[j];
        grow[j] = t[j] * n;  // self-loop contribution of layer 2
    }
}

// Layer-2 edge aggregation: agg2[dst] += t[src] * dinv[src]*dinv[dst]
__global__ void k_agg2(const int* __restrict__ src, const int* __restrict__ dst) {
    int e = blockIdx.x * blockDim.x + threadIdx.x;
    if (e >= NE) return;
    int s = src[e];
    int d = dst[e];
    float w = g_dinv[s] * g_dinv[d];
    const float4* __restrict__ tr = reinterpret_cast<const float4*>(g_t + (size_t)s * H2);
    float4 t0 = tr[0];
    float4 t1 = tr[1];
    float4* out = reinterpret_cast<float4*>(g_agg2 + (size_t)d * H2);
    atomicAdd(out,     make_float4(t0.x * w, t0.y * w, t0.z * w, t0.w * w));
    atomicAdd(out + 1, make_float4(t1.x * w, t1.y * w, t1.z * w, t1.w * w));
}

__global__ void k_h2(const float* __restrict__ b2) {
    int tid = blockIdx.x * blockDim.x + threadIdx.x;
    if (tid >= NN * H2) return;
    g_h2[tid] = g_agg2[tid] + b2[tid & (H2 - 1)];
}

// Edge score: sigmoid(dot(h2[src], h2[dst]))
__global__ void k_score(const int* __restrict__ src, const int* __restrict__ dst,
                        float* __restrict__ out) {
    int e = blockIdx.x * blockDim.x + threadIdx.x;
    if (e >= NE) return;
    int s = src[e];
    int d = dst[e];
    const float4* __restrict__ hs = reinterpret_cast<const float4*>(g_h2 + (size_t)s * H2);
    const float4* __restrict__ hd = reinterpret_cast<const float4*>(g_h2 + (size_t)d * H2);
    float4 a0 = hs[0], a1 = hs[1];
    float4 c0 = hd[0], c1 = hd[1];
    float sc = a0.x * c0.x + a0.y * c0.y + a0.z * c0.z + a0.w * c0.w
             + a1.x * c1.x + a1.y * c1.y + a1.z * c1.z + a1.w * c1.w;
    out[e] = 1.0f / (1.0f + __expf(-sc));
}

// ---------------------------------------------------------------------------
extern "C" void kernel_launch(void* const* d_in, const int* in_sizes, int n_in,
                              void* d_out, int out_size) {
    const float* x  = (const float*)d_in[0];
    const int*   ei = (const int*)  d_in[1];
    const float* W1 = (const float*)d_in[2];
    const float* b1 = (const float*)d_in[3];
    const float* W2 = (const float*)d_in[4];
    const float* b2 = (const float*)d_in[5];
    float* out = (float*)d_out;

    const int* src = ei;        // edge_index[0]
    const int* dst = ei + NE;   // edge_index[1]

    constexpr int TB = 256;
    k_deg_init<<<(NN + TB - 1) / TB, TB>>>();
    k_deg     <<<(NE + TB - 1) / TB, TB>>>(dst);
    k_dinv    <<<(NN + TB - 1) / TB, TB>>>();
    k_prep    <<<(NN * FP + TB - 1) / TB, TB>>>(x);
    k_agg1    <<<(NE + TB - 1) / TB, TB>>>(src, dst);
    k_layer   <<<(NN + TB - 1) / TB, TB>>>(W1, b1, W2);
    k_agg2    <<<(NE + TB - 1) / TB, TB>>>(src, dst);
    k_h2      <<<(NN * H2 + TB - 1) / TB, TB>>>(b2);
    k_score   <<<(NE + TB - 1) / TB, TB>>>(src, dst, out);
}

// round 2
// speedup vs baseline: 1.5569x; 1.5569x over previous
#include <cuda_runtime.h>
#include <math.h>

// Problem constants (fixed by the reference setup_inputs)
constexpr int NN  = 100000;   // nodes
constexpr int NE  = 3200000;  // edges
constexpr int FIN = 21;       // input features
constexpr int FP  = 24;       // padded feature row (96B)
constexpr int H1  = 32;
constexpr int H2  = 8;
constexpr int CHUNK = 2048;                       // scan chunk per block
constexpr int NB    = (NN + CHUNK - 1) / CHUNK;   // 49 scan blocks

// Scratch (device globals; allocation is forbidden)
__device__ int   g_cnt   [NN];      // in-degree histogram (real edges only)
__device__ int   g_off   [NN];      // CSR row start
__device__ int   g_cursor[NN];      // scatter cursors
__device__ int   g_bsum  [64];      // scan block sums
__device__ int   g_csrc  [NE];      // CSR: source node per slot
__device__ float g_dinv  [NN];
__device__ __align__(16) float g_xn  [NN * FP];  // x * dinv[src], padded
__device__ __align__(16) float g_agg1[NN * FP];
__device__ __align__(16) float g_tn  [NN * H2];  // (h1@W2) * dinv
__device__ __align__(16) float g_h2  [NN * H2];

// ---------------------------------------------------------------------------
__global__ void k_zero() {
    int i = blockIdx.x * blockDim.x + threadIdx.x;
    if (i < NN) g_cnt[i] = 0;
}

__global__ void k_hist(const int* __restrict__ dst) {
    int e = blockIdx.x * blockDim.x + threadIdx.x;
    if (e < NE) atomicAdd(&g_cnt[dst[e]], 1);
}

// Block-level exclusive scan over chunks of 2048; block totals to g_bsum.
__global__ void k_scan1() {
    int t = threadIdx.x;                 // 1024 threads
    int base = blockIdx.x * CHUNK;
    int i0 = base + 2 * t, i1 = i0 + 1;
    int a = (i0 < NN) ? g_cnt[i0] : 0;
    int b = (i1 < NN) ? g_cnt[i1] : 0;
    int s = a + b;
    int lane = t & 31, wid = t >> 5;
    int inc = s;
#pragma unroll
    for (int o = 1; o < 32; o <<= 1) {
        int n = __shfl_up_sync(0xffffffffu, inc, o);
        if (lane >= o) inc += n;
    }
    __shared__ int ws[32];
    if (lane == 31) ws[wid] = inc;
    __syncthreads();
    if (wid == 0) {
        int w = ws[lane];
#pragma unroll
        for (int o = 1; o < 32; o <<= 1) {
            int n = __shfl_up_sync(0xffffffffu, w, o);
            if (lane >= o) w += n;
        }
        ws[lane] = w;
    }
    __syncthreads();
    int off  = (wid > 0) ? ws[wid - 1] : 0;
    int excl = off + inc - s;
    if (i0 < NN) g_off[i0] = excl;
    if (i1 < NN) g_off[i1] = excl + a;
    if (t == 0) g_bsum[blockIdx.x] = ws[31];
}

// Exclusive scan of the 49 block sums (single block of 64 threads).
__global__ void k_scan2() {
    int t = threadIdx.x;
    int v = (t < NB) ? g_bsum[t] : 0;
    int lane = t & 31, wid = t >> 5;
    int inc = v;
#pragma unroll
    for (int o = 1; o < 32; o <<= 1) {
        int n = __shfl_up_sync(0xffffffffu, inc, o);
        if (lane >= o) inc += n;
    }
    __shared__ int ws[2];
    if (lane == 31) ws[wid] = inc;
    __syncthreads();
    int excl = inc - v + ((wid == 1) ? ws[0] : 0);
    if (t < NB) g_bsum[t] = excl;
}

// Finalize offsets, init cursors, compute dinv (deg = cnt + 1 self-loop).
__global__ void k_scan3() {
    int i = blockIdx.x * blockDim.x + threadIdx.x;
    if (i >= NN) return;
    int o = g_off[i] + g_bsum[i >> 11];
    g_off[i] = o;
    g_cursor[i] = o;
    g_dinv[i] = rsqrtf((float)g_cnt[i] + 1.0f);
}

__global__ void k_scatter(const int* __restrict__ src, const int* __restrict__ dst) {
    int e = blockIdx.x * blockDim.x + threadIdx.x;
    if (e >= NE) return;
    int pos = atomicAdd(&g_cursor[dst[e]], 1);
    g_csrc[pos] = src[e];
}

// xn = x * dinv[row], padded to 24 floats.
__global__ void k_prep(const float* __restrict__ x) {
    int tid = blockIdx.x * blockDim.x + threadIdx.x;
    if (tid >= NN * FP) return;
    int i = tid / FP;
    int f = tid - i * FP;
    float v = (f < FIN) ? x[i * FIN + f] : 0.0f;
    g_xn[tid] = v * g_dinv[i];
}

// Layer-1 gather: one warp per node, lane = feature (24 active).
// agg1[d] = dinv[d] * (xn[d] + sum_{src in in(d)} xn[src])
__global__ void k_gagg1() {
    int w = (blockIdx.x * blockDim.x + threadIdx.x) >> 5;
    if (w >= NN) return;
    int lane = threadIdx.x & 31;
    int start = g_off[w];
    int deg   = g_cnt[w];
    float acc = (lane < FP) ? g_xn[w * FP + lane] : 0.0f;
    for (int j = 0; j < deg; j++) {
        int s = g_csrc[start + j];
        if (lane < FP) acc += g_xn[s * FP + lane];
    }
    if (lane < FP) g_agg1[w * FP + lane] = acc * g_dinv[w];
}

// Per node: h1 = relu(agg1 @ W1 + b1); tn = (h1 @ W2) * dinv
__global__ void k_layer(const float* __restrict__ W1, const float* __restrict__ b1,
                        const float* __restrict__ W2) {
    __shared__ float sW1[FIN * H1];
    __shared__ float sW2[H1 * H2];
    __shared__ float sb1[H1];
    for (int j = threadIdx.x; j < FIN * H1; j += blockDim.x) sW1[j] = W1[j];
    for (int j = threadIdx.x; j < H1 * H2; j += blockDim.x) sW2[j] = W2[j];
    for (int j = threadIdx.x; j < H1; j += blockDim.x) sb1[j] = b1[j];
    __syncthreads();

    int i = blockIdx.x * blockDim.x + threadIdx.x;
    if (i >= NN) return;

    float a[FIN];
    const float* __restrict__ arow = g_agg1 + (size_t)i * FP;
#pragma unroll
    for (int f = 0; f < FIN; f++) a[f] = arow[f];

    float t[H2];
#pragma unroll
    for (int j = 0; j < H2; j++) t[j] = 0.0f;

#pragma unroll
    for (int k = 0; k < H1; k++) {
        float acc = sb1[k];
#pragma unroll
        for (int f = 0; f < FIN; f++) acc = fmaf(a[f], sW1[f * H1 + k], acc);
        acc = fmaxf(acc, 0.0f);
#pragma unroll
        for (int j = 0; j < H2; j++) t[j] = fmaf(acc, sW2[k * H2 + j], t[j]);
    }

    float di = g_dinv[i];
    float* trow = g_tn + (size_t)i * H2;
#pragma unroll
    for (int j = 0; j < H2; j++) trow[j] = t[j] * di;
}

// Layer-2 gather: 8 threads per node (lane group = feature).
// h2[d] = dinv[d] * (tn[d] + sum tn[src]) + b2
__global__ void k_gagg2(const float* __restrict__ b2) {
    int tid = blockIdx.x * blockDim.x + threadIdx.x;
    int node = tid >> 3;
    if (node >= NN) return;
    int f = tid & 7;
    int start = g_off[node];
    int deg   = g_cnt[node];
    float acc = g_tn[node * H2 + f];
    for (int j = 0; j < deg; j++) {
        int s = g_csrc[start + j];
        acc += g_tn[s * H2 + f];
    }
    g_h2[node * H2 + f] = acc * g_dinv[node] + b2[f];
}

// Edge score: sigmoid(dot(h2[src], h2[dst]))
__global__ void k_score(const int* __restrict__ src, const int* __restrict__ dst,
                        float* __restrict__ out) {
    int e = blockIdx.x * blockDim.x + threadIdx.x;
    if (e >= NE) return;
    int s = src[e];
    int d = dst[e];
    const float4* __restrict__ hs = reinterpret_cast<const float4*>(g_h2 + (size_t)s * H2);
    const float4* __restrict__ hd = reinterpret_cast<const float4*>(g_h2 + (size_t)d * H2);
    float4 a0 = hs[0], a1 = hs[1];
    float4 c0 = hd[0], c1 = hd[1];
    float sc = a0.x * c0.x + a0.y * c0.y + a0.z * c0.z + a0.w * c0.w
             + a1.x * c1.x + a1.y * c1.y + a1.z * c1.z + a1.w * c1.w;
    out[e] = 1.0f / (1.0f + __expf(-sc));
}

// ---------------------------------------------------------------------------
extern "C" void kernel_launch(void* const* d_in, const int* in_sizes, int n_in,
                              void* d_out, int out_size) {
    const float* x  = (const float*)d_in[0];
    const int*   ei = (const int*)  d_in[1];
    const float* W1 = (const float*)d_in[2];
    const float* b1 = (const float*)d_in[3];
    const float* W2 = (const float*)d_in[4];
    const float* b2 = (const float*)d_in[5];
    float* out = (float*)d_out;

    const int* src = ei;        // edge_index[0]
    const int* dst = ei + NE;   // edge_index[1]

    constexpr int TB = 256;
    k_zero   <<<(NN + TB - 1) / TB, TB>>>();
    k_hist   <<<(NE + TB - 1) / TB, TB>>>(dst);
    k_scan1  <<<NB, 1024>>>();
    k_scan2  <<<1, 64>>>();
    k_scan3  <<<(NN + TB - 1) / TB, TB>>>();
    k_scatter<<<(NE + TB - 1) / TB, TB>>>(src, dst);
    k_prep   <<<(NN * FP + TB - 1) / TB, TB>>>(x);
    k_gagg1  <<<(NN * 32 + TB - 1) / TB, TB>>>();
    k_layer  <<<(NN + TB - 1) / TB, TB>>>(W1, b1, W2);
    k_gagg2  <<<(NN * H2 + TB - 1) / TB, TB>>>(b2);
    k_score  <<<(NE + TB - 1) / TB, TB>>>(src, dst, out);
}